// round 1
// baseline (speedup 1.0000x reference)
#include <cuda_runtime.h>
#include <cstdint>
#include <cstddef>

// ---------------- problem constants ----------------
#define B_    4
#define DIM_  512
#define T_    2048
#define CB    14               // codebook_dim
#define NS    (B_ * T_)        // 8192 samples
#define J_    16384            // 2^14 codes
#define OUT_ELEMS (B_ * DIM_ * T_)   // 4194304
#define IDX_OFF   OUT_ELEMS          // indices start
#define AUX_OFF   (OUT_ELEMS + NS)   // aux loss scalar

// ---------------- scratch (no allocation allowed) ----------------
__device__ float  g_h[NS * CB];      // projected h values
__device__ float  g_avg[J_];         // sum of probs per code
__device__ double g_scal[2];         // [0]=commit_sum, [1]=per-sample-entropy sum

// =====================================================================
// Kernel A: fused input GEMM (h = x @ W_in^T + b_in), sign quantization,
// indices, commitment loss, per-sample entropy (factorized Bernoulli),
// and output projection out = q @ W_out^T + b_out (q = +-1 exactly).
//
// grid = 128 blocks: b = blk>>5, t-tile of 64 at t0 = (blk&31)*64.
// block = 128 threads: lane2 = tid&31 owns 2 consecutive t's (float2),
//                      dgrp  = tid>>5 owns a 128-wide d-slice.
// =====================================================================
__global__ __launch_bounds__(128) void lfq_kA(
    const float* __restrict__ x,
    const float* __restrict__ Win,
    const float* __restrict__ bin,
    const float* __restrict__ Wout,
    const float* __restrict__ bout,
    float* __restrict__ out)
{
    extern __shared__ float sm[];
    float* sWin  = sm;                     // 14*512 = 7168
    float* sWout = sWin  + CB * DIM_;      // 512*14 = 7168
    float* sBin  = sWout + DIM_ * CB;      // 16
    float* sBout = sBin  + 16;             // 512
    float* sPart = sBout + DIM_;           // 4*64*14 = 3584
    float* sH    = sPart + 4 * 64 * CB;    // 64*15 = 960 (padded vs bank conflicts)
    float* sRed  = sH    + 64 * 15;        // 16 used

    const int tid = threadIdx.x;
    const int blk = blockIdx.x;
    const int b   = blk >> 5;
    const int t0  = (blk & 31) * 64;

    // cooperative loads of weights into shared
    {
        const float4* s4 = (const float4*)Win;
        float4*       d4 = (float4*)sWin;
        #pragma unroll 4
        for (int i = tid; i < CB * DIM_ / 4; i += 128) d4[i] = s4[i];
        s4 = (const float4*)Wout;
        d4 = (float4*)sWout;
        #pragma unroll 4
        for (int i = tid; i < DIM_ * CB / 4; i += 128) d4[i] = s4[i];
        if (tid < CB) sBin[tid] = bin[tid];
        for (int i = tid; i < DIM_; i += 128) sBout[i] = bout[i];
    }
    __syncthreads();

    const int lane2 = tid & 31;
    const int dgrp  = tid >> 5;
    const int tl    = lane2 * 2;

    // ------------- phase 1: h GEMM (partial over 128 d's) -------------
    float acc0[CB], acc1[CB];
    #pragma unroll
    for (int c = 0; c < CB; ++c) { acc0[c] = 0.f; acc1[c] = 0.f; }

    const float* xp    = x + ((size_t)(b * DIM_ + dgrp * 128)) * T_ + t0 + tl;
    const float* wbase = sWin + dgrp * 128;
    #pragma unroll 2
    for (int di = 0; di < 128; ++di) {
        float2 xv = *(const float2*)(xp + (size_t)di * T_);
        #pragma unroll
        for (int c = 0; c < CB; ++c) {
            float w = wbase[c * DIM_ + di];     // uniform per warp -> LDS broadcast
            acc0[c] = fmaf(w, xv.x, acc0[c]);
            acc1[c] = fmaf(w, xv.y, acc1[c]);
        }
    }
    #pragma unroll
    for (int c = 0; c < CB; ++c) {
        sPart[((dgrp * 64) + tl)     * CB + c] = acc0[c];
        sPart[((dgrp * 64) + tl + 1) * CB + c] = acc1[c];
    }
    __syncthreads();

    // ------------- combine partials: 64 t * 14 c = 896 items -------------
    #pragma unroll
    for (int it = 0; it < 7; ++it) {
        int idx = tid + it * 128;          // < 896
        int t   = idx / CB;
        int c   = idx - t * CB;
        float h = sBin[c];
        #pragma unroll
        for (int g = 0; g < 4; ++g) h += sPart[(g * 64 + t) * CB + c];
        sH[t * 15 + c] = h;
        g_h[(size_t)(b * T_ + t0 + t) * CB + c] = h;
    }
    __syncthreads();

    // ------------- per-sample stats: indices, commit, entropy -------------
    float lc = 0.f, le = 0.f;
    if (tid < 64) {
        const int t = tid;
        int index = 0;
        #pragma unroll
        for (int c = 0; c < CB; ++c) {
            float h   = sH[t * 15 + c];
            int   bit = h > 0.f;
            index |= bit << (13 - c);
            float q = bit ? 1.f : -1.f;
            float d = h - q;
            lc = fmaf(d, d, lc);
            // H(sigmoid(z)) with z = 400*h :  log(1+e^-|z|) + |z| e^-|z| / (1+e^-|z|)
            float z = fabsf(400.f * h);
            float e = __expf(-z);
            le += __logf(1.f + e) + z * e / (1.f + e);
        }
        out[IDX_OFF + b * T_ + t0 + t] = (float)index;
    }
    #pragma unroll
    for (int off = 16; off > 0; off >>= 1) {
        lc += __shfl_down_sync(0xffffffffu, lc, off);
        le += __shfl_down_sync(0xffffffffu, le, off);
    }
    const int wid = tid >> 5, lid = tid & 31;
    if (lid == 0) { sRed[wid] = lc; sRed[8 + wid] = le; }
    __syncthreads();
    if (tid == 0) {
        float c4 = sRed[0] + sRed[1] + sRed[2] + sRed[3];
        float e4 = sRed[8] + sRed[9] + sRed[10] + sRed[11];
        atomicAdd(&g_scal[0], (double)c4);
        atomicAdd(&g_scal[1], (double)e4);
    }

    // ------------- phase 2: output projection (q = +-1 exactly) -------------
    float s0[CB], s1[CB];
    #pragma unroll
    for (int c = 0; c < CB; ++c) {
        s0[c] = sH[tl       * 15 + c] > 0.f ? 1.f : -1.f;
        s1[c] = sH[(tl + 1) * 15 + c] > 0.f ? 1.f : -1.f;
    }
    float* op = out + ((size_t)(b * DIM_ + dgrp * 128)) * T_ + t0 + tl;
    #pragma unroll 2
    for (int di = 0; di < 128; ++di) {
        const int    d = dgrp * 128 + di;
        const float* w = sWout + d * CB;     // uniform per warp -> broadcast
        float o0 = sBout[d], o1 = o0;
        #pragma unroll
        for (int c = 0; c < CB; ++c) {
            float wv = w[c];
            o0 = fmaf(s0[c], wv, o0);
            o1 = fmaf(s1[c], wv, o1);
        }
        *(float2*)(op + (size_t)di * T_) = make_float2(o0, o1);
    }
}

// =====================================================================
// Kernel C: avg_prob accumulation using the Bernoulli factorization.
// p_j = A[j>>7] * B[j&127];  A from bits 13..7 (c=0..6), B from bits 6..0.
// grid = 128 blocks x 256 threads; each block owns 64 samples; each
// thread keeps 64 register accumulators over a fixed j-subset, merged
// into g_avg with one atomicAdd per entry at the end.
// =====================================================================
__global__ __launch_bounds__(256) void lfq_kC()
{
    __shared__ float sP[16];
    __shared__ float sA[128];
    __shared__ float sB[128];

    const int tid = threadIdx.x;
    const int s0  = blockIdx.x * 64;

    float acc[64];
    #pragma unroll
    for (int k = 0; k < 64; ++k) acc[k] = 0.f;

    const int hi  = tid >> 1;
    const int par = tid & 1;

    for (int i = 0; i < 64; ++i) {
        if (tid < CB) {
            float h = g_h[(size_t)(s0 + i) * CB + tid];
            sP[tid] = 1.f / (1.f + __expf(-400.f * h));  // P(bit c set)
        }
        __syncthreads();
        if (tid < 128) {
            float v = 1.f;
            #pragma unroll
            for (int c = 0; c < 7; ++c) {
                float pc = sP[c];
                v *= ((tid >> (6 - c)) & 1) ? pc : (1.f - pc);
            }
            sA[tid] = v;
        } else {
            const int lo = tid - 128;
            float v = 1.f;
            #pragma unroll
            for (int c = 7; c < CB; ++c) {
                float pc = sP[c];
                v *= ((lo >> (13 - c)) & 1) ? pc : (1.f - pc);
            }
            sB[lo] = v;
        }
        __syncthreads();
        float a = sA[hi];
        #pragma unroll
        for (int k = 0; k < 64; ++k)
            acc[k] = fmaf(a, sB[par + 2 * k], acc[k]);
        __syncthreads();
    }

    float* base = g_avg + hi * 128 + par;
    #pragma unroll
    for (int k = 0; k < 64; ++k)
        atomicAdd(base + 2 * k, acc[k]);
}

// =====================================================================
// Kernel D: finalize — codebook entropy over 16384 codes + combine
// =====================================================================
__global__ __launch_bounds__(256) void lfq_kD(float* __restrict__ out)
{
    __shared__ double sr[256];
    const int tid = threadIdx.x;
    double s = 0.0;
    for (int j = tid; j < J_; j += 256) {
        double a  = (double)g_avg[j] * (1.0 / (double)NS);
        double cl = a < 1e-20 ? 1e-20 : a;
        s -= a * log(cl);
    }
    sr[tid] = s;
    __syncthreads();
    for (int off = 128; off > 0; off >>= 1) {
        if (tid < off) sr[tid] += sr[tid + off];
        __syncthreads();
    }
    if (tid == 0) {
        double psent  = g_scal[1] / (double)NS;                 // per_sample_entropy
        double commit = g_scal[0] / ((double)NS * (double)CB);  // commitment MSE
        double aux    = (psent - sr[0]) * 0.1 + commit;         // gamma=1, ent_w=0.1, commit_w=1
        out[AUX_OFF] = (float)aux;
    }
}

// =====================================================================
extern "C" void kernel_launch(void* const* d_in, const int* in_sizes, int n_in,
                              void* d_out, int out_size)
{
    (void)in_sizes; (void)n_in; (void)out_size;
    const float* x    = (const float*)d_in[0];
    const float* Win  = (const float*)d_in[1];
    const float* bin  = (const float*)d_in[2];
    const float* Wout = (const float*)d_in[3];
    const float* bout = (const float*)d_in[4];
    float*       out  = (float*)d_out;

    // zero the cross-kernel accumulators (graph-capturable memsets)
    void* avgp = nullptr;
    void* scp  = nullptr;
    cudaGetSymbolAddress(&avgp, g_avg);
    cudaGetSymbolAddress(&scp,  g_scal);
    cudaMemsetAsync(avgp, 0, J_ * sizeof(float));
    cudaMemsetAsync(scp,  0, 2 * sizeof(double));

    const int SMEM_A = (CB*DIM_ + DIM_*CB + 16 + DIM_ + 4*64*CB + 64*15 + 16) * (int)sizeof(float);
    cudaFuncSetAttribute(lfq_kA, cudaFuncAttributeMaxDynamicSharedMemorySize, SMEM_A);

    lfq_kA<<<128, 128, SMEM_A>>>(x, Win, bin, Wout, bout, out);
    lfq_kC<<<128, 256>>>();
    lfq_kD<<<1, 256>>>(out);
}

// round 2
// speedup vs baseline: 2.9921x; 2.9921x over previous
#include <cuda_runtime.h>
#include <cstdint>
#include <cstddef>

// ---------------- problem constants ----------------
#define B_    4
#define DIM_  512
#define T_    2048
#define CB    14               // codebook_dim
#define NS    (B_ * T_)        // 8192 samples
#define J_    16384            // 2^14 codes
#define OUT_ELEMS (B_ * DIM_ * T_)   // 4194304
#define IDX_OFF   OUT_ELEMS
#define AUX_OFF   (OUT_ELEMS + NS)

// ---------------- global scratch ----------------
__device__ float  g_avg[J_];         // sum of probs per code
__device__ double g_scal[3];         // [0]=commit, [1]=per-sample entropy, [2]=codebook entropy

// ---------------- shared-memory layout (float offsets) ----------------
#define OFF_WIN   0                          // 14*512
#define OFF_WOUT  (OFF_WIN + CB*DIM_)        // 512*14
#define OFF_BIN   (OFF_WOUT + DIM_*CB)       // 16
#define OFF_BOUT  (OFF_BIN + 16)             // 512
#define OFF_PART  (OFF_BOUT + DIM_)          // 8*64*14 = 7168
#define OFF_H     (OFF_PART + 8*64*CB)       // 64*16
#define OFF_RED   (OFF_H + 64*16)            // 32
#define OFF_P     (OFF_RED + 32)             // 64*16 sigmoids
#define OFF_A     (OFF_P + 64*16)            // 64*128
#define OFF_B     (OFF_A + 64*128)           // 64*128
#define SMEM_FLOATS (OFF_B + 64*128)         // 40496 floats = 161984 B

// =====================================================================
// Fused kernel: input GEMM + quantize + indices + commit/entropy stats
// + output projection + avg_prob rank-1 accumulation (register-tiled).
// grid = 128 (b = blk>>5, t-tile of 64), block = 256 threads.
// =====================================================================
__global__ __launch_bounds__(256, 1) void lfq_fused(
    const float* __restrict__ x,
    const float* __restrict__ Win,
    const float* __restrict__ bin,
    const float* __restrict__ Wout,
    const float* __restrict__ bout,
    float* __restrict__ out)
{
    extern __shared__ float sm[];
    const int tid = threadIdx.x;
    const int blk = blockIdx.x;
    const int b   = blk >> 5;
    const int t0  = (blk & 31) * 64;

    // ---- load weights into shared ----
    {
        const float4* s4 = (const float4*)Win;
        float4*       d4 = (float4*)(sm + OFF_WIN);
        #pragma unroll 4
        for (int i = tid; i < CB * DIM_ / 4; i += 256) d4[i] = s4[i];
        s4 = (const float4*)Wout;
        d4 = (float4*)(sm + OFF_WOUT);
        #pragma unroll 4
        for (int i = tid; i < DIM_ * CB / 4; i += 256) d4[i] = s4[i];
        if (tid < CB) sm[OFF_BIN + tid] = bin[tid];
        for (int i = tid; i < DIM_; i += 256) sm[OFF_BOUT + i] = bout[i];
    }
    __syncthreads();

    const int lane32 = tid & 31;
    const int dgrp   = tid >> 5;       // 0..7, each owns 64 d's
    const int tl     = lane32 * 2;     // t within tile (float2)

    // ---- phase 1: h GEMM partials over 64 d's per warp ----
    float acc0[CB], acc1[CB];
    #pragma unroll
    for (int c = 0; c < CB; ++c) { acc0[c] = 0.f; acc1[c] = 0.f; }

    const float* xp = x + ((size_t)(b * DIM_ + dgrp * 64)) * T_ + t0 + tl;
    const float* wb = sm + OFF_WIN + dgrp * 64;
    #pragma unroll 4
    for (int di = 0; di < 64; ++di) {
        float2 xv = *(const float2*)(xp + (size_t)di * T_);
        #pragma unroll
        for (int c = 0; c < CB; ++c) {
            float w = wb[c * DIM_ + di];      // uniform per warp -> broadcast
            acc0[c] = fmaf(w, xv.x, acc0[c]);
            acc1[c] = fmaf(w, xv.y, acc1[c]);
        }
    }
    {
        float* part = sm + OFF_PART + dgrp * (64 * CB);
        #pragma unroll
        for (int c = 0; c < CB; ++c) {
            part[tl       * CB + c] = acc0[c];
            part[(tl + 1) * CB + c] = acc1[c];
        }
    }
    __syncthreads();

    // ---- phase 1b: combine 8 partials -> sH ----
    #pragma unroll
    for (int it = 0; it < 4; ++it) {
        int idx = tid + it * 256;
        if (idx < 64 * CB) {
            int t = idx / CB;
            int c = idx - t * CB;
            float h = sm[OFF_BIN + c];
            #pragma unroll
            for (int g = 0; g < 8; ++g) h += sm[OFF_PART + g * (64 * CB) + t * CB + c];
            sm[OFF_H + t * 16 + c] = h;
        }
    }
    __syncthreads();

    // ---- phase 1c: indices, commit, per-sample entropy ----
    float lc = 0.f, le = 0.f;
    if (tid < 64) {
        int index = 0;
        #pragma unroll
        for (int c = 0; c < CB; ++c) {
            float h   = sm[OFF_H + tid * 16 + c];
            int   bit = h > 0.f;
            index |= bit << (13 - c);
            float q = bit ? 1.f : -1.f;
            float d = h - q;
            lc = fmaf(d, d, lc);
            float z = fabsf(400.f * h);
            float e = __expf(-z);
            le += __logf(1.f + e) + z * e / (1.f + e);
        }
        out[IDX_OFF + b * T_ + t0 + tid] = (float)index;
    }
    #pragma unroll
    for (int off = 16; off > 0; off >>= 1) {
        lc += __shfl_down_sync(0xffffffffu, lc, off);
        le += __shfl_down_sync(0xffffffffu, le, off);
    }
    if (lane32 == 0) { sm[OFF_RED + dgrp] = lc; sm[OFF_RED + 8 + dgrp] = le; }
    __syncthreads();
    if (tid == 0) {
        atomicAdd(&g_scal[0], (double)(sm[OFF_RED]     + sm[OFF_RED + 1]));
        atomicAdd(&g_scal[1], (double)(sm[OFF_RED + 8] + sm[OFF_RED + 9]));
    }

    // ---- phase 2: out projection, q = +-1 exactly ----
    {
        float s0[CB], s1[CB];
        #pragma unroll
        for (int c = 0; c < CB; ++c) {
            s0[c] = sm[OFF_H + tl       * 16 + c] > 0.f ? 1.f : -1.f;
            s1[c] = sm[OFF_H + (tl + 1) * 16 + c] > 0.f ? 1.f : -1.f;
        }
        float* op = out + ((size_t)(b * DIM_ + dgrp * 64)) * T_ + t0 + tl;
        const float* wo = sm + OFF_WOUT + (dgrp * 64) * CB;
        #pragma unroll 2
        for (int di = 0; di < 64; ++di) {
            const float* w = wo + di * CB;    // uniform per warp -> broadcast
            float o0 = sm[OFF_BOUT + dgrp * 64 + di], o1 = o0;
            #pragma unroll
            for (int c = 0; c < CB; ++c) {
                float wv = w[c];
                o0 = fmaf(s0[c], wv, o0);
                o1 = fmaf(s1[c], wv, o1);
            }
            *(float2*)(op + (size_t)di * T_) = make_float2(o0, o1);
        }
    }

    // ---- phase 3a: sigmoids for all 64 samples ----
    #pragma unroll
    for (int it = 0; it < 4; ++it) {
        int idx = tid + it * 256;
        if (idx < 64 * CB) {
            int t = idx / CB;
            int c = idx - t * CB;
            float h = sm[OFF_H + t * 16 + c];
            sm[OFF_P + t * 16 + c] = 1.f / (1.f + __expf(-400.f * h));
        }
    }
    __syncthreads();

    // ---- phase 3b: half-products A (bits 13..7) and B (bits 6..0) ----
    for (int idx = tid; idx < 64 * 128; idx += 256) {
        int i = idx >> 7;          // sample
        int v = idx & 127;         // 7-bit pattern
        const float* p = sm + OFF_P + i * 16;
        float a = 1.f, bb = 1.f;
        #pragma unroll
        for (int c = 0; c < 7; ++c) {
            int bit = (v >> (6 - c)) & 1;
            float pa = p[c];
            float pb = p[7 + c];
            a  *= bit ? pa : 1.f - pa;
            bb *= bit ? pb : 1.f - pb;
        }
        sm[OFF_A + idx] = a;
        sm[OFF_B + idx] = bb;
    }
    __syncthreads();

    // ---- phase 3c: G += sum_i A_i (x) B_i, 8x8 register tile per thread ----
    {
        const int ty = tid >> 4, tx = tid & 15;
        const float* pA = sm + OFF_A + ty * 8;
        const float* pB = sm + OFF_B + tx * 8;
        float G[8][8];
        #pragma unroll
        for (int r = 0; r < 8; ++r)
            #pragma unroll
            for (int c = 0; c < 8; ++c) G[r][c] = 0.f;

        #pragma unroll 2
        for (int i = 0; i < 64; ++i) {
            float4 a0 = *(const float4*)(pA + i * 128);
            float4 a1 = *(const float4*)(pA + i * 128 + 4);
            float4 b0 = *(const float4*)(pB + i * 128);
            float4 b1 = *(const float4*)(pB + i * 128 + 4);
            float av[8] = {a0.x, a0.y, a0.z, a0.w, a1.x, a1.y, a1.z, a1.w};
            float bv[8] = {b0.x, b0.y, b0.z, b0.w, b1.x, b1.y, b1.z, b1.w};
            #pragma unroll
            for (int r = 0; r < 8; ++r)
                #pragma unroll
                for (int c = 0; c < 8; ++c)
                    G[r][c] = fmaf(av[r], bv[c], G[r][c]);
        }
        float* gp = g_avg + (ty * 8) * 128 + tx * 8;
        #pragma unroll
        for (int r = 0; r < 8; ++r)
            #pragma unroll
            for (int c = 0; c < 8; ++c)
                atomicAdd(gp + r * 128 + c, G[r][c]);
    }
}

// =====================================================================
// Codebook entropy: 16 blocks x 1024 threads, one j each, fp32 log.
// =====================================================================
__global__ __launch_bounds__(1024) void lfq_ent()
{
    __shared__ float sr[32];
    const int j = blockIdx.x * 1024 + threadIdx.x;
    float a  = g_avg[j] * (1.f / (float)NS);
    float cl = fmaxf(a, 1e-20f);
    float term = -a * __logf(cl);
    #pragma unroll
    for (int off = 16; off > 0; off >>= 1)
        term += __shfl_down_sync(0xffffffffu, term, off);
    const int wid = threadIdx.x >> 5, lid = threadIdx.x & 31;
    if (lid == 0) sr[wid] = term;
    __syncthreads();
    if (wid == 0) {
        float v = sr[lid];
        #pragma unroll
        for (int off = 16; off > 0; off >>= 1)
            v += __shfl_down_sync(0xffffffffu, v, off);
        if (lid == 0) atomicAdd(&g_scal[2], (double)v);
    }
}

// =====================================================================
// Final combine (1 thread)
// =====================================================================
__global__ void lfq_fin(float* __restrict__ out)
{
    double psent  = g_scal[1] / (double)NS;
    double commit = g_scal[0] / ((double)NS * (double)CB);
    double aux    = (psent - g_scal[2]) * 0.1 + commit;
    out[AUX_OFF] = (float)aux;
}

// =====================================================================
extern "C" void kernel_launch(void* const* d_in, const int* in_sizes, int n_in,
                              void* d_out, int out_size)
{
    (void)in_sizes; (void)n_in; (void)out_size;
    const float* x    = (const float*)d_in[0];
    const float* Win  = (const float*)d_in[1];
    const float* bin  = (const float*)d_in[2];
    const float* Wout = (const float*)d_in[3];
    const float* bout = (const float*)d_in[4];
    float*       out  = (float*)d_out;

    void* avgp = nullptr;
    void* scp  = nullptr;
    cudaGetSymbolAddress(&avgp, g_avg);
    cudaGetSymbolAddress(&scp,  g_scal);
    cudaMemsetAsync(avgp, 0, J_ * sizeof(float));
    cudaMemsetAsync(scp,  0, 3 * sizeof(double));

    const int SMEM_A = SMEM_FLOATS * (int)sizeof(float);
    cudaFuncSetAttribute(lfq_fused, cudaFuncAttributeMaxDynamicSharedMemorySize, SMEM_A);

    lfq_fused<<<128, 256, SMEM_A>>>(x, Win, bin, Wout, bout, out);
    lfq_ent<<<16, 1024>>>();
    lfq_fin<<<1, 1>>>(out);
}

// round 4
// speedup vs baseline: 6.5960x; 2.2045x over previous
#include <cuda_runtime.h>
#include <cstdint>
#include <cstddef>

// ---------------- problem constants ----------------
#define B_    4
#define DIM_  512
#define T_    2048
#define CB    14               // codebook_dim
#define NS    (B_ * T_)        // 8192 samples
#define J_    16384            // 2^14 codes
#define OUT_ELEMS (B_ * DIM_ * T_)   // 4194304
#define IDX_OFF   OUT_ELEMS
#define AUX_OFF   (OUT_ELEMS + NS)

#define TT    32               // t-tile per block
#define ZSAT  20.0f            // |400h| beyond this => sigmoid saturated in fp32 sense

// ---------------- global scratch ----------------
__device__ float  g_avg[J_];         // sum of probs per code
__device__ double g_scal[3];         // [0]=commit, [1]=per-sample entropy, [2]=codebook entropy

// ---------------- shared layout (float offsets) ----------------
#define OFF_WIN   0                          // 14*512 = 7168
#define OFF_WOUT  (OFF_WIN + CB*DIM_)        // 512*14 = 7168
#define OFF_BIN   (OFF_WOUT + DIM_*CB)       // 16
#define OFF_BOUT  (OFF_BIN + 16)             // 512
#define OFF_PART  (OFF_BOUT + DIM_)          // 8*32*14 = 3584
#define OFF_H     (OFF_PART + 8*TT*CB)       // 32*17 = 544 (pad 17 => conflict-free)
#define OFF_RED   (OFF_H + TT*17)            // 32
#define SMEM_FLOATS (OFF_RED + 32)           // ~19.5k floats = ~78 KB

// =====================================================================
// Fused kernel. grid = 256 (b = blk>>6, t0 = (blk&63)*32), block = 256.
// Each warp owns 64 d's; each lane owns one t (t = t0 + lane).
// =====================================================================
__global__ __launch_bounds__(256, 2) void lfq_fused(
    const float* __restrict__ x,
    const float* __restrict__ Win,
    const float* __restrict__ bin,
    const float* __restrict__ Wout,
    const float* __restrict__ bout,
    float* __restrict__ out)
{
    extern __shared__ float sm[];
    const int tid  = threadIdx.x;
    const int blk  = blockIdx.x;
    const int b    = blk >> 6;
    const int t0   = (blk & 63) * TT;
    const int lane = tid & 31;
    const int warp = tid >> 5;          // 0..7, owns d in [warp*64, warp*64+64)

    // ---- cooperative weight load ----
    {
        const float4* s4 = (const float4*)Win;
        float4*       d4 = (float4*)(sm + OFF_WIN);
        #pragma unroll 4
        for (int i = tid; i < CB * DIM_ / 4; i += 256) d4[i] = s4[i];
        s4 = (const float4*)Wout;
        d4 = (float4*)(sm + OFF_WOUT);
        #pragma unroll 4
        for (int i = tid; i < DIM_ * CB / 4; i += 256) d4[i] = s4[i];
        if (tid < CB) sm[OFF_BIN + tid] = bin[tid];
        for (int i = tid; i < DIM_; i += 256) sm[OFF_BOUT + i] = bout[i];
    }
    __syncthreads();

    // ---- phase 1: h partials, each warp over its 64 d's ----
    float acc[CB];
    #pragma unroll
    for (int c = 0; c < CB; ++c) acc[c] = 0.f;

    const float* xp = x + ((size_t)(b * DIM_ + warp * 64)) * T_ + t0 + lane;
    const float* wb = sm + OFF_WIN + warp * 64;
    #pragma unroll 8
    for (int di = 0; di < 64; ++di) {
        float xv = xp[(size_t)di * T_];          // 128B coalesced per warp
        #pragma unroll
        for (int c = 0; c < CB; ++c)
            acc[c] = fmaf(wb[c * DIM_ + di], xv, acc[c]);  // LDS broadcast
    }
    {
        float* part = sm + OFF_PART + warp * (TT * CB) + lane * CB;
        #pragma unroll
        for (int c = 0; c < CB; ++c) part[c] = acc[c];
    }
    __syncthreads();

    // ---- phase 1b: combine 8 partials -> sH (448 items) ----
    #pragma unroll
    for (int it = 0; it < 2; ++it) {
        int idx = tid + it * 256;
        if (idx < TT * CB) {
            int t = idx / CB;
            int c = idx - t * CB;
            float h = sm[OFF_BIN + c];
            #pragma unroll
            for (int g = 0; g < 8; ++g) h += sm[OFF_PART + g * (TT * CB) + t * CB + c];
            sm[OFF_H + t * 17 + c] = h;
        }
    }
    __syncthreads();

    // ---- phase 2: out projection (all threads), q = +-1 exactly ----
    {
        float s[CB];
        #pragma unroll
        for (int c = 0; c < CB; ++c)
            s[c] = sm[OFF_H + lane * 17 + c] > 0.f ? 1.f : -1.f;   // pitch 17: conflict-free
        float* op = out + ((size_t)(b * DIM_ + warp * 64)) * T_ + t0 + lane;
        const float* wo = sm + OFF_WOUT + (warp * 64) * CB;
        #pragma unroll 4
        for (int di = 0; di < 64; ++di) {
            const float* w = wo + di * CB;        // uniform -> broadcast
            float o = sm[OFF_BOUT + warp * 64 + di];
            #pragma unroll
            for (int c = 0; c < CB; ++c) o = fmaf(s[c], w[c], o);
            op[(size_t)di * T_] = o;              // 128B coalesced
        }
    }

    // ---- phase 3 (warp 0 only, no sync needed): stats + sparse avg_prob ----
    if (tid < 32) {
        const int t = tid;
        int   index = 0;
        float lc = 0.f, le = 0.f;
        int   base  = 0;            // saturated-bit code
        int   n_unc = 0;
        float pu[CB];               // uncertain-bit probabilities
        int   mu[CB];               // their bit masks
        #pragma unroll
        for (int c = 0; c < CB; ++c) {
            float h   = sm[OFF_H + t * 17 + c];
            int   bit = h > 0.f;
            index |= bit << (13 - c);
            float q = bit ? 1.f : -1.f;
            float d = h - q;
            lc = fmaf(d, d, lc);
            float z  = 400.f * h;
            float az = fabsf(z);
            if (az <= ZSAT) {
                float e = __expf(-az);
                le += __logf(1.f + e) + az * e / (1.f + e);
                pu[n_unc] = 1.f / (1.f + __expf(-z));   // P(bit set)
                mu[n_unc] = 1 << (13 - c);
                ++n_unc;
            } else if (bit) {
                base |= 1 << (13 - c);
            }
        }
        out[IDX_OFF + b * T_ + t0 + t] = (float)index;

        // enumerate 2^n_unc codes (almost always 1 or 2)
        const int nsub = 1 << n_unc;
        for (int s2 = 0; s2 < nsub; ++s2) {
            int   code = base;
            float prod = 1.f;
            for (int k = 0; k < n_unc; ++k) {
                if ((s2 >> k) & 1) { code |= mu[k]; prod *= pu[k]; }
                else               {                prod *= 1.f - pu[k]; }
            }
            atomicAdd(&g_avg[code], prod);
        }

        // warp-reduce commit / per-sample entropy
        #pragma unroll
        for (int off = 16; off > 0; off >>= 1) {
            lc += __shfl_down_sync(0xffffffffu, lc, off);
            le += __shfl_down_sync(0xffffffffu, le, off);
        }
        if (lane == 0) {
            atomicAdd(&g_scal[0], (double)lc);
            atomicAdd(&g_scal[1], (double)le);
        }
    }
}

// =====================================================================
// Codebook entropy: 16 blocks x 1024 threads
// =====================================================================
__global__ __launch_bounds__(1024) void lfq_ent()
{
    __shared__ float sr[32];
    const int j = blockIdx.x * 1024 + threadIdx.x;
    float a  = g_avg[j] * (1.f / (float)NS);
    float cl = fmaxf(a, 1e-20f);
    float term = -a * __logf(cl);
    #pragma unroll
    for (int off = 16; off > 0; off >>= 1)
        term += __shfl_down_sync(0xffffffffu, term, off);
    const int wid = threadIdx.x >> 5, lid = threadIdx.x & 31;
    if (lid == 0) sr[wid] = term;
    __syncthreads();
    if (wid == 0) {
        float v = sr[lid];
        #pragma unroll
        for (int off = 16; off > 0; off >>= 1)
            v += __shfl_down_sync(0xffffffffu, v, off);
        if (lid == 0) atomicAdd(&g_scal[2], (double)v);
    }
}

__global__ void lfq_fin(float* __restrict__ out)
{
    double psent  = g_scal[1] / (double)NS;
    double commit = g_scal[0] / ((double)NS * (double)CB);
    double aux    = (psent - g_scal[2]) * 0.1 + commit;
    out[AUX_OFF] = (float)aux;
}

// =====================================================================
extern "C" void kernel_launch(void* const* d_in, const int* in_sizes, int n_in,
                              void* d_out, int out_size)
{
    (void)in_sizes; (void)n_in; (void)out_size;
    const float* x    = (const float*)d_in[0];
    const float* Win  = (const float*)d_in[1];
    const float* bin  = (const float*)d_in[2];
    const float* Wout = (const float*)d_in[3];
    const float* bout = (const float*)d_in[4];
    float*       out  = (float*)d_out;

    void* avgp = nullptr;
    void* scp  = nullptr;
    cudaGetSymbolAddress(&avgp, g_avg);
    cudaGetSymbolAddress(&scp,  g_scal);
    cudaMemsetAsync(avgp, 0, J_ * sizeof(float));
    cudaMemsetAsync(scp,  0, 3 * sizeof(double));

    const int SMEM_A = SMEM_FLOATS * (int)sizeof(float);
    cudaFuncSetAttribute(lfq_fused, cudaFuncAttributeMaxDynamicSharedMemorySize, SMEM_A);

    lfq_fused<<<256, 256, SMEM_A>>>(x, Win, bin, Wout, bout, out);
    lfq_ent<<<16, 1024>>>();
    lfq_fin<<<1, 1>>>(out);
}